// round 13
// baseline (speedup 1.0000x reference)
#include <cuda_runtime.h>
#include <math.h>

#define BATCH 8
#define NPTS  4096
#define HH    256
#define KOUT  1024
#define NC    63
#define CAP   512           // smem member capacity (E[cnt]=64 -> 50+ sigma margin)

// ---------------------------------------------------------------------------
// Single kernel. Block (b,c): c in [0,63) = cluster block, c==63 = noise rows.
// Phase 1: branchless bitmask scan -> member index list (ints only).
// Phase 2: parallel scattered gather of member x into smem + query collection.
// Phase 3: HALF-WARP per query: 16-lane attention + MLP, xor-butterfly
//          reductions (4 levels, no broadcasts). Pre-folded weights:
//   score(x_m) = qk·x_m + qb,   qk = M·x_q + u,  qb = wb·x_q + s0
//   o          = N·mean + p     (k/v/ctx never materialized)
// ---------------------------------------------------------------------------
__global__ __launch_bounds__(256, 4)
void fused_kernel(const float* __restrict__ x,
                  const int*   __restrict__ labels,
                  const float* __restrict__ Wq, const float* __restrict__ bq,
                  const float* __restrict__ Wk, const float* __restrict__ bk,
                  const float* __restrict__ Wv, const float* __restrict__ bv,
                  const float* __restrict__ Wo, const float* __restrict__ bo,
                  const float* __restrict__ W1, const float* __restrict__ b1,
                  const float* __restrict__ W2, const float* __restrict__ b2,
                  float* __restrict__ out)
{
    __shared__ float4 sx[CAP];            // member x (w unused)
    __shared__ short  smidx[CAP];         // member original row n (0..4095)
    __shared__ int    sq[CAP];            // (sx pos << 16) | query row n
    __shared__ float4 sW1p[HH];           // (W1[3j], W1[3j+1], W1[3j+2], b1[j])
    __shared__ float4 sW2p[HH];           // (W2[j], W2[HH+j], W2[2HH+j], 0)
    __shared__ float  sM[9], su[3], swb[3], sNw[9], sp[3], s_s0;
    __shared__ int    s_cnt, s_qn;
    __shared__ float  s_y3[3];

    const int tid  = threadIdx.x;
    const int warp = tid >> 5;
    const int lane = tid & 31;
    const int b    = blockIdx.x >> 6;
    const int c    = blockIdx.x & 63;

    const int*   lab = labels + b * NPTS;
    const float* xb  = x + (size_t)b * NPTS * 3;

    // Stage MLP weights packed (one j per thread; 256 == HH)
    {
        const int j = tid;
        sW1p[j] = make_float4(W1[3*j], W1[3*j+1], W1[3*j+2], b1[j]);
        sW2p[j] = make_float4(W2[j], W2[HH + j], W2[2*HH + j], 0.f);
    }

    // ---------------- noise block: constant output for label==-1 rows --------
    if (c == NC) {
        __syncthreads();
        if (warp == 0) {
            float o0 = __ldg(bo + 0), o1 = __ldg(bo + 1), o2 = __ldg(bo + 2);
            float y0 = 0.f, y1 = 0.f, y2 = 0.f;
#pragma unroll
            for (int t = 0; t < HH / 32; t++) {
                int j = lane + t * 32;
                float4 w = sW1p[j];
                float h = fmaf(w.x, o0, fmaf(w.y, o1, fmaf(w.z, o2, w.w)));
                h = fmaxf(h, 0.f);
                float4 u = sW2p[j];
                y0 = fmaf(u.x, h, y0);
                y1 = fmaf(u.y, h, y1);
                y2 = fmaf(u.z, h, y2);
            }
#pragma unroll
            for (int off = 16; off; off >>= 1) {
                y0 += __shfl_down_sync(0xffffffffu, y0, off);
                y1 += __shfl_down_sync(0xffffffffu, y1, off);
                y2 += __shfl_down_sync(0xffffffffu, y2, off);
            }
            if (lane == 0) {
                s_y3[0] = y0 + __ldg(b2 + 0);
                s_y3[1] = y1 + __ldg(b2 + 1);
                s_y3[2] = y2 + __ldg(b2 + 2);
            }
        }
        __syncthreads();
        float y0 = s_y3[0], y1 = s_y3[1], y2 = s_y3[2];
        const int4 L = reinterpret_cast<const int4*>(lab)[tid];
        const int n0 = tid * 4;
        if (L.x == -1) { float* op = out + (size_t)(b*KOUT + n0    )*3; op[0]=y0; op[1]=y1; op[2]=y2; }
        if (L.y == -1) { float* op = out + (size_t)(b*KOUT + n0 + 1)*3; op[0]=y0; op[1]=y1; op[2]=y2; }
        if (L.z == -1) { float* op = out + (size_t)(b*KOUT + n0 + 2)*3; op[0]=y0; op[1]=y1; op[2]=y2; }
        if (L.w == -1) { float* op = out + (size_t)(b*KOUT + n0 + 3)*3; op[0]=y0; op[1]=y1; op[2]=y2; }
        return;
    }

    // ---------------- cluster block ----------------
    if (tid == 0) { s_cnt = 0; s_qn = 0; }
    __syncthreads();

    // Phase 1: branchless bitmask scan (bit bi = t*4+j -> row t*1024 + tid*4 + j)
    const int4* lab4 = reinterpret_cast<const int4*>(lab);
    unsigned mask = 0;
#pragma unroll
    for (int t = 0; t < 4; t++) {
        const int4 L = lab4[t * 256 + tid];
        mask |= (unsigned)(L.x == c) << (t * 4 + 0);
        mask |= (unsigned)(L.y == c) << (t * 4 + 1);
        mask |= (unsigned)(L.z == c) << (t * 4 + 2);
        mask |= (unsigned)(L.w == c) << (t * 4 + 3);
    }
    const int nbase = tid * 4;
    while (mask) {
        const int bi = __ffs(mask) - 1;
        mask &= mask - 1;
        const int n = ((bi >> 2) << 10) + nbase + (bi & 3);
        const int p = atomicAdd(&s_cnt, 1);
        if (p < CAP) smidx[p] = (short)n;
    }

    // Parallel prefold: 28 threads, one folded scalar each.
    if (tid < 28) {
        const float scale = 0.57735026919f;   // 1/sqrt(3)
        const int i = tid;
        if (i < 9) {
            int cc = i / 3, d = i % 3;
            sM[i] = scale * (__ldg(Wq+d)  *__ldg(Wk+cc)
                           + __ldg(Wq+3+d)*__ldg(Wk+3+cc)
                           + __ldg(Wq+6+d)*__ldg(Wk+6+cc));
        } else if (i < 12) {
            int cc = i - 9;
            su[cc] = scale * (__ldg(bq+0)*__ldg(Wk+cc)
                            + __ldg(bq+1)*__ldg(Wk+3+cc)
                            + __ldg(bq+2)*__ldg(Wk+6+cc));
        } else if (i < 15) {
            int cc = i - 12;
            swb[cc] = scale * (__ldg(bk+0)*__ldg(Wq+cc)
                             + __ldg(bk+1)*__ldg(Wq+3+cc)
                             + __ldg(bk+2)*__ldg(Wq+6+cc));
        } else if (i == 15) {
            s_s0 = scale * (__ldg(bk+0)*__ldg(bq+0)
                          + __ldg(bk+1)*__ldg(bq+1)
                          + __ldg(bk+2)*__ldg(bq+2));
        } else if (i < 25) {
            int r = (i - 16) / 3, cc = (i - 16) % 3;
            sNw[i-16] = __ldg(Wo+r*3+0)*__ldg(Wv+cc)
                      + __ldg(Wo+r*3+1)*__ldg(Wv+3+cc)
                      + __ldg(Wo+r*3+2)*__ldg(Wv+6+cc);
        } else {
            int r = i - 25;
            sp[r] = __ldg(Wo+r*3+0)*__ldg(bv+0)
                  + __ldg(Wo+r*3+1)*__ldg(bv+1)
                  + __ldg(Wo+r*3+2)*__ldg(bv+2) + __ldg(bo+r);
        }
    }
    __syncthreads();

    const int cnt = min(s_cnt, CAP);

    // Phase 2: parallel gather of member x + query collection (cnt < 256 typ.)
    for (int i = tid; i < cnt; i += 256) {
        const int n = smidx[i];
        const float* xv = xb + (size_t)n * 3;
        sx[i] = make_float4(xv[0], xv[1], xv[2], 0.f);
        if (n < KOUT) {
            int qp = atomicAdd(&s_qn, 1);
            sq[qp] = n | (i << 16);
        }
    }
    __syncthreads();

    const int qn = s_qn;
    if (qn == 0) return;

    const float b20 = __ldg(b2 + 0), b21 = __ldg(b2 + 1), b22 = __ldg(b2 + 2);

    // Phase 3: one query per HALF-WARP (two per warp), xor-butterfly reduces.
    const int half  = lane >> 4;          // 0 or 1
    const int hlane = lane & 15;
    for (int qq0 = warp * 2; qq0 < qn; qq0 += 16) {
        const int  qq   = qq0 + half;
        const bool live = qq < qn;
        const int  e    = sq[live ? qq : qq0];
        const int  nq   = e & 0xFFFF, pq = e >> 16;

        const float4 xq = sx[pq];
        const float qk0 = fmaf(sM[0], xq.x, fmaf(sM[1], xq.y, fmaf(sM[2], xq.z, su[0])));
        const float qk1 = fmaf(sM[3], xq.x, fmaf(sM[4], xq.y, fmaf(sM[5], xq.z, su[1])));
        const float qk2 = fmaf(sM[6], xq.x, fmaf(sM[7], xq.y, fmaf(sM[8], xq.z, su[2])));
        const float qb  = fmaf(swb[0], xq.x, fmaf(swb[1], xq.y, fmaf(swb[2], xq.z, s_s0)));

        // plain-exp softmax over member x, 16 lanes, stride 16
        float sm = 0.f, a0 = 0.f, a1 = 0.f, a2 = 0.f;
        for (int i = hlane; i < cnt; i += 16) {
            const float4 xm = sx[i];
            const float s = fmaf(qk0, xm.x, fmaf(qk1, xm.y, fmaf(qk2, xm.z, qb)));
            const float e2 = __expf(s);
            sm += e2;
            a0 = fmaf(e2, xm.x, a0);
            a1 = fmaf(e2, xm.y, a1);
            a2 = fmaf(e2, xm.z, a2);
        }
        // xor butterfly within 16-lane segment: all lanes get the sum
#pragma unroll
        for (int off = 8; off; off >>= 1) {
            sm += __shfl_xor_sync(0xffffffffu, sm, off, 16);
            a0 += __shfl_xor_sync(0xffffffffu, a0, off, 16);
            a1 += __shfl_xor_sync(0xffffffffu, a1, off, 16);
            a2 += __shfl_xor_sync(0xffffffffu, a2, off, 16);
        }
        const float inv = 1.f / sm;           // sm > 0: query is its own member
        const float m0 = a0 * inv, m1 = a1 * inv, m2 = a2 * inv;

        const float o0 = fmaf(sNw[0], m0, fmaf(sNw[1], m1, fmaf(sNw[2], m2, sp[0])));
        const float o1 = fmaf(sNw[3], m0, fmaf(sNw[4], m1, fmaf(sNw[5], m2, sp[1])));
        const float o2 = fmaf(sNw[6], m0, fmaf(sNw[7], m1, fmaf(sNw[8], m2, sp[2])));

        // MLP: 16 hidden units per lane (j depends only on hlane -> both
        // halves hit the same 16 addresses: 2x fewer smem wavefronts)
        float y0 = 0.f, y1 = 0.f, y2 = 0.f;
#pragma unroll
        for (int t = 0; t < HH / 16; t++) {
            const int j = hlane + t * 16;
            const float4 w = sW1p[j];
            float h = fmaf(w.x, o0, fmaf(w.y, o1, fmaf(w.z, o2, w.w)));
            h = fmaxf(h, 0.f);
            const float4 u = sW2p[j];
            y0 = fmaf(u.x, h, y0);
            y1 = fmaf(u.y, h, y1);
            y2 = fmaf(u.z, h, y2);
        }
#pragma unroll
        for (int off = 8; off; off >>= 1) {
            y0 += __shfl_xor_sync(0xffffffffu, y0, off, 16);
            y1 += __shfl_xor_sync(0xffffffffu, y1, off, 16);
            y2 += __shfl_xor_sync(0xffffffffu, y2, off, 16);
        }
        if (hlane == 0 && live) {
            float* op = out + (size_t)(b * KOUT + nq) * 3;
            op[0] = y0 + b20; op[1] = y1 + b21; op[2] = y2 + b22;
        }
    }
}

// ---------------------------------------------------------------------------
extern "C" void kernel_launch(void* const* d_in, const int* in_sizes, int n_in,
                              void* d_out, int out_size)
{
    const float* x      = (const float*)d_in[0];
    const int*   labels = (const int*)  d_in[1];
    const float* Wq = (const float*)d_in[2];
    const float* bq = (const float*)d_in[3];
    const float* Wk = (const float*)d_in[4];
    const float* bk = (const float*)d_in[5];
    const float* Wv = (const float*)d_in[6];
    const float* bv = (const float*)d_in[7];
    const float* Wo = (const float*)d_in[8];
    const float* bo = (const float*)d_in[9];
    const float* W1 = (const float*)d_in[10];
    const float* b1 = (const float*)d_in[11];
    const float* W2 = (const float*)d_in[12];
    const float* b2 = (const float*)d_in[13];
    float* out = (float*)d_out;

    fused_kernel<<<BATCH * 64, 256>>>(x, labels, Wq, bq, Wk, bk, Wv, bv,
                                      Wo, bo, W1, b1, W2, b2, out);
}

// round 14
// speedup vs baseline: 1.0150x; 1.0150x over previous
#include <cuda_runtime.h>
#include <math.h>

#define BATCH 8
#define NPTS  4096
#define HH    256
#define KOUT  1024
#define NC    63
#define CAP   512           // smem member capacity (E[cnt]=64 -> 50+ sigma margin)

// ---------------------------------------------------------------------------
// Single kernel. Block (b,c): c in [0,63) = cluster block, c==63 = noise rows.
// Phase 1: branchless bitmask scan -> member index list + query list (ints).
// Phase 2: parallel scattered gather of member x into smem (pure loads).
// Phase 3: dual-query warp attention + packed-f4 MLP, xor-butterfly reduces.
//   score(x_m) = qk·x_m + qb,   qk = M·x_q + u,  qb = wb·x_q + s0
//   o          = N·mean + p     (k/v/ctx never materialized)
// ---------------------------------------------------------------------------
__global__ __launch_bounds__(256, 4)
void fused_kernel(const float* __restrict__ x,
                  const int*   __restrict__ labels,
                  const float* __restrict__ Wq, const float* __restrict__ bq,
                  const float* __restrict__ Wk, const float* __restrict__ bk,
                  const float* __restrict__ Wv, const float* __restrict__ bv,
                  const float* __restrict__ Wo, const float* __restrict__ bo,
                  const float* __restrict__ W1, const float* __restrict__ b1,
                  const float* __restrict__ W2, const float* __restrict__ b2,
                  float* __restrict__ out)
{
    __shared__ float4 sx[CAP];            // member x (w unused)
    __shared__ short  smidx[CAP];         // member original row n (0..4095)
    __shared__ int    sq[CAP];            // (sx pos << 16) | query row n
    __shared__ float4 sW1p[HH];           // (W1[3j], W1[3j+1], W1[3j+2], b1[j])
    __shared__ float4 sW2p[HH];           // (W2[j], W2[HH+j], W2[2HH+j], 0)
    __shared__ float  sM[9], su[3], swb[3], sNw[9], sp[3], s_s0;
    __shared__ int    s_cnt, s_qn;
    __shared__ float  s_y3[3];

    const int tid  = threadIdx.x;
    const int warp = tid >> 5;
    const int lane = tid & 31;
    const int b    = blockIdx.x >> 6;
    const int c    = blockIdx.x & 63;

    const int*   lab = labels + b * NPTS;
    const float* xb  = x + (size_t)b * NPTS * 3;

    // Stage MLP weights packed (one j per thread; 256 == HH)
    {
        const int j = tid;
        sW1p[j] = make_float4(W1[3*j], W1[3*j+1], W1[3*j+2], b1[j]);
        sW2p[j] = make_float4(W2[j], W2[HH + j], W2[2*HH + j], 0.f);
    }

    // ---------------- noise block: constant output for label==-1 rows --------
    if (c == NC) {
        __syncthreads();
        if (warp == 0) {
            float o0 = __ldg(bo + 0), o1 = __ldg(bo + 1), o2 = __ldg(bo + 2);
            float y0 = 0.f, y1 = 0.f, y2 = 0.f;
#pragma unroll
            for (int t = 0; t < HH / 32; t++) {
                int j = lane + t * 32;
                float4 w = sW1p[j];
                float h = fmaf(w.x, o0, fmaf(w.y, o1, fmaf(w.z, o2, w.w)));
                h = fmaxf(h, 0.f);
                float4 u = sW2p[j];
                y0 = fmaf(u.x, h, y0);
                y1 = fmaf(u.y, h, y1);
                y2 = fmaf(u.z, h, y2);
            }
#pragma unroll
            for (int off = 16; off; off >>= 1) {
                y0 += __shfl_xor_sync(0xffffffffu, y0, off);
                y1 += __shfl_xor_sync(0xffffffffu, y1, off);
                y2 += __shfl_xor_sync(0xffffffffu, y2, off);
            }
            if (lane == 0) {
                s_y3[0] = y0 + __ldg(b2 + 0);
                s_y3[1] = y1 + __ldg(b2 + 1);
                s_y3[2] = y2 + __ldg(b2 + 2);
            }
        }
        __syncthreads();
        float y0 = s_y3[0], y1 = s_y3[1], y2 = s_y3[2];
        const int4 L = reinterpret_cast<const int4*>(lab)[tid];
        const int n0 = tid * 4;
        if (L.x == -1) { float* op = out + (size_t)(b*KOUT + n0    )*3; op[0]=y0; op[1]=y1; op[2]=y2; }
        if (L.y == -1) { float* op = out + (size_t)(b*KOUT + n0 + 1)*3; op[0]=y0; op[1]=y1; op[2]=y2; }
        if (L.z == -1) { float* op = out + (size_t)(b*KOUT + n0 + 2)*3; op[0]=y0; op[1]=y1; op[2]=y2; }
        if (L.w == -1) { float* op = out + (size_t)(b*KOUT + n0 + 3)*3; op[0]=y0; op[1]=y1; op[2]=y2; }
        return;
    }

    // ---------------- cluster block ----------------
    if (tid == 0) { s_cnt = 0; s_qn = 0; }
    __syncthreads();

    // Phase 1: branchless bitmask scan (bit bi = t*4+j -> row t*1024 + tid*4 + j)
    const int4* lab4 = reinterpret_cast<const int4*>(lab);
    unsigned mask = 0;
#pragma unroll
    for (int t = 0; t < 4; t++) {
        const int4 L = lab4[t * 256 + tid];
        mask |= (unsigned)(L.x == c) << (t * 4 + 0);
        mask |= (unsigned)(L.y == c) << (t * 4 + 1);
        mask |= (unsigned)(L.z == c) << (t * 4 + 2);
        mask |= (unsigned)(L.w == c) << (t * 4 + 3);
    }
    const int nbase = tid * 4;
    while (mask) {
        const int bi = __ffs(mask) - 1;
        mask &= mask - 1;
        const int n = ((bi >> 2) << 10) + nbase + (bi & 3);
        const int p = atomicAdd(&s_cnt, 1);
        if (p < CAP) {
            smidx[p] = (short)n;
            if (bi < 4) {                       // bi<4 <=> n < KOUT
                const int qp = atomicAdd(&s_qn, 1);
                sq[qp] = n | (p << 16);
            }
        }
    }

    // Parallel prefold: 28 threads, one folded scalar each.
    if (tid < 28) {
        const float scale = 0.57735026919f;   // 1/sqrt(3)
        const int i = tid;
        if (i < 9) {
            int cc = i / 3, d = i % 3;
            sM[i] = scale * (__ldg(Wq+d)  *__ldg(Wk+cc)
                           + __ldg(Wq+3+d)*__ldg(Wk+3+cc)
                           + __ldg(Wq+6+d)*__ldg(Wk+6+cc));
        } else if (i < 12) {
            int cc = i - 9;
            su[cc] = scale * (__ldg(bq+0)*__ldg(Wk+cc)
                            + __ldg(bq+1)*__ldg(Wk+3+cc)
                            + __ldg(bq+2)*__ldg(Wk+6+cc));
        } else if (i < 15) {
            int cc = i - 12;
            swb[cc] = scale * (__ldg(bk+0)*__ldg(Wq+cc)
                             + __ldg(bk+1)*__ldg(Wq+3+cc)
                             + __ldg(bk+2)*__ldg(Wq+6+cc));
        } else if (i == 15) {
            s_s0 = scale * (__ldg(bk+0)*__ldg(bq+0)
                          + __ldg(bk+1)*__ldg(bq+1)
                          + __ldg(bk+2)*__ldg(bq+2));
        } else if (i < 25) {
            int r = (i - 16) / 3, cc = (i - 16) % 3;
            sNw[i-16] = __ldg(Wo+r*3+0)*__ldg(Wv+cc)
                      + __ldg(Wo+r*3+1)*__ldg(Wv+3+cc)
                      + __ldg(Wo+r*3+2)*__ldg(Wv+6+cc);
        } else {
            int r = i - 25;
            sp[r] = __ldg(Wo+r*3+0)*__ldg(bv+0)
                  + __ldg(Wo+r*3+1)*__ldg(bv+1)
                  + __ldg(Wo+r*3+2)*__ldg(bv+2) + __ldg(bo+r);
        }
    }
    __syncthreads();

    const int cnt = min(s_cnt, CAP);

    // Phase 2: pure parallel gather of member x (cnt < 256 typ., no atomics)
    for (int i = tid; i < cnt; i += 256) {
        const int n = smidx[i];
        const float* xv = xb + (size_t)n * 3;
        sx[i] = make_float4(xv[0], xv[1], xv[2], 0.f);
    }
    __syncthreads();

    const int qn = s_qn;
    if (qn == 0) return;

    const float b20 = __ldg(b2 + 0), b21 = __ldg(b2 + 1), b22 = __ldg(b2 + 2);

    // Phase 3: two queries per warp per round (shared smem loads)
    for (int qq = warp * 2; qq < qn; qq += 16) {
        const int  e0   = sq[qq];
        const bool has2 = (qq + 1) < qn;
        const int  e1   = has2 ? sq[qq + 1] : e0;
        const int  n0q  = e0 & 0xFFFF, p0 = e0 >> 16;
        const int  n1q  = e1 & 0xFFFF, p1 = e1 >> 16;

        const float4 xqa = sx[p0];
        const float4 xqb = sx[p1];

        const float qkA0 = fmaf(sM[0], xqa.x, fmaf(sM[1], xqa.y, fmaf(sM[2], xqa.z, su[0])));
        const float qkA1 = fmaf(sM[3], xqa.x, fmaf(sM[4], xqa.y, fmaf(sM[5], xqa.z, su[1])));
        const float qkA2 = fmaf(sM[6], xqa.x, fmaf(sM[7], xqa.y, fmaf(sM[8], xqa.z, su[2])));
        const float qbA  = fmaf(swb[0], xqa.x, fmaf(swb[1], xqa.y, fmaf(swb[2], xqa.z, s_s0)));
        const float qkB0 = fmaf(sM[0], xqb.x, fmaf(sM[1], xqb.y, fmaf(sM[2], xqb.z, su[0])));
        const float qkB1 = fmaf(sM[3], xqb.x, fmaf(sM[4], xqb.y, fmaf(sM[5], xqb.z, su[1])));
        const float qkB2 = fmaf(sM[6], xqb.x, fmaf(sM[7], xqb.y, fmaf(sM[8], xqb.z, su[2])));
        const float qbB  = fmaf(swb[0], xqb.x, fmaf(swb[1], xqb.y, fmaf(swb[2], xqb.z, s_s0)));

        // dual plain-exp softmax; one sx load feeds both queries
        float smA = 0.f, aA0 = 0.f, aA1 = 0.f, aA2 = 0.f;
        float smB = 0.f, aB0 = 0.f, aB1 = 0.f, aB2 = 0.f;
        for (int i = lane; i < cnt; i += 32) {
            const float4 xm = sx[i];
            const float sA = fmaf(qkA0, xm.x, fmaf(qkA1, xm.y, fmaf(qkA2, xm.z, qbA)));
            const float sB = fmaf(qkB0, xm.x, fmaf(qkB1, xm.y, fmaf(qkB2, xm.z, qbB)));
            const float eA = __expf(sA);
            const float eB = __expf(sB);
            smA += eA; smB += eB;
            aA0 = fmaf(eA, xm.x, aA0); aB0 = fmaf(eB, xm.x, aB0);
            aA1 = fmaf(eA, xm.y, aA1); aB1 = fmaf(eB, xm.y, aB1);
            aA2 = fmaf(eA, xm.z, aA2); aB2 = fmaf(eB, xm.z, aB2);
        }
        // width-32 xor butterfly: all lanes end with the total, no broadcasts
#pragma unroll
        for (int off = 16; off; off >>= 1) {
            smA += __shfl_xor_sync(0xffffffffu, smA, off);
            aA0 += __shfl_xor_sync(0xffffffffu, aA0, off);
            aA1 += __shfl_xor_sync(0xffffffffu, aA1, off);
            aA2 += __shfl_xor_sync(0xffffffffu, aA2, off);
            smB += __shfl_xor_sync(0xffffffffu, smB, off);
            aB0 += __shfl_xor_sync(0xffffffffu, aB0, off);
            aB1 += __shfl_xor_sync(0xffffffffu, aB1, off);
            aB2 += __shfl_xor_sync(0xffffffffu, aB2, off);
        }

        const float invA = __fdividef(1.f, smA);
        const float invB = __fdividef(1.f, smB);
        const float mA0 = aA0 * invA, mA1 = aA1 * invA, mA2 = aA2 * invA;
        const float mB0 = aB0 * invB, mB1 = aB1 * invB, mB2 = aB2 * invB;

        const float oA0 = fmaf(sNw[0], mA0, fmaf(sNw[1], mA1, fmaf(sNw[2], mA2, sp[0])));
        const float oA1 = fmaf(sNw[3], mA0, fmaf(sNw[4], mA1, fmaf(sNw[5], mA2, sp[1])));
        const float oA2 = fmaf(sNw[6], mA0, fmaf(sNw[7], mA1, fmaf(sNw[8], mA2, sp[2])));
        const float oB0 = fmaf(sNw[0], mB0, fmaf(sNw[1], mB1, fmaf(sNw[2], mB2, sp[0])));
        const float oB1 = fmaf(sNw[3], mB0, fmaf(sNw[4], mB1, fmaf(sNw[5], mB2, sp[1])));
        const float oB2 = fmaf(sNw[6], mB0, fmaf(sNw[7], mB1, fmaf(sNw[8], mB2, sp[2])));

        // dual MLP: packed float4 weights -> 2 LDS.128 per iter, no addr math
        float yA0 = 0.f, yA1 = 0.f, yA2 = 0.f;
        float yB0 = 0.f, yB1 = 0.f, yB2 = 0.f;
#pragma unroll
        for (int t = 0; t < HH / 32; t++) {
            const int j = lane + t * 32;
            const float4 w = sW1p[j];
            float hA = fmaf(w.x, oA0, fmaf(w.y, oA1, fmaf(w.z, oA2, w.w)));
            float hB = fmaf(w.x, oB0, fmaf(w.y, oB1, fmaf(w.z, oB2, w.w)));
            hA = fmaxf(hA, 0.f); hB = fmaxf(hB, 0.f);
            const float4 u = sW2p[j];
            yA0 = fmaf(u.x, hA, yA0); yB0 = fmaf(u.x, hB, yB0);
            yA1 = fmaf(u.y, hA, yA1); yB1 = fmaf(u.y, hB, yB1);
            yA2 = fmaf(u.z, hA, yA2); yB2 = fmaf(u.z, hB, yB2);
        }
#pragma unroll
        for (int off = 16; off; off >>= 1) {
            yA0 += __shfl_xor_sync(0xffffffffu, yA0, off);
            yA1 += __shfl_xor_sync(0xffffffffu, yA1, off);
            yA2 += __shfl_xor_sync(0xffffffffu, yA2, off);
            yB0 += __shfl_xor_sync(0xffffffffu, yB0, off);
            yB1 += __shfl_xor_sync(0xffffffffu, yB1, off);
            yB2 += __shfl_xor_sync(0xffffffffu, yB2, off);
        }
        if (lane == 0) {
            float* op = out + (size_t)(b * KOUT + n0q) * 3;
            op[0] = yA0 + b20; op[1] = yA1 + b21; op[2] = yA2 + b22;
            if (has2) {
                float* oq = out + (size_t)(b * KOUT + n1q) * 3;
                oq[0] = yB0 + b20; oq[1] = yB1 + b21; oq[2] = yB2 + b22;
            }
        }
    }
}

// ---------------------------------------------------------------------------
extern "C" void kernel_launch(void* const* d_in, const int* in_sizes, int n_in,
                              void* d_out, int out_size)
{
    const float* x      = (const float*)d_in[0];
    const int*   labels = (const int*)  d_in[1];
    const float* Wq = (const float*)d_in[2];
    const float* bq = (const float*)d_in[3];
    const float* Wk = (const float*)d_in[4];
    const float* bk = (const float*)d_in[5];
    const float* Wv = (const float*)d_in[6];
    const float* bv = (const float*)d_in[7];
    const float* Wo = (const float*)d_in[8];
    const float* bo = (const float*)d_in[9];
    const float* W1 = (const float*)d_in[10];
    const float* b1 = (const float*)d_in[11];
    const float* W2 = (const float*)d_in[12];
    const float* b2 = (const float*)d_in[13];
    float* out = (float*)d_out;

    fused_kernel<<<BATCH * 64, 256>>>(x, labels, Wq, bq, Wk, bk, Wv, bv,
                                      Wo, bo, W1, b1, W2, b2, out);
}